// round 4
// baseline (speedup 1.0000x reference)
#include <cuda_runtime.h>
#include <cuda_bf16.h>
#include <math.h>

#define Hh 1024
#define Ww 1024
#define Nn 32
#define NCOLS 32768
#define NELEM (Nn * Hh * Ww)      // 33554432
#define SLEN 16                   // rows per segment
#define NSEG 64                   // segments per column
#define NCQ (NCOLS / 4)           // 8192 column-quads
#define K1_THREADS (NCQ * NSEG)   // 524288

// Scratch (__device__ globals: allocation-free per harness rules)
__device__ unsigned g_dl[NELEM / 4];     // 32 MB: per byte = (pb<<7) | d_local(7b), element order
__device__ unsigned g_A [NSEG * NCQ];    // 2 MB fwd seg aggregates (4 col-bytes per uint)
__device__ unsigned g_B [NSEG * NCQ];    // 2 MB bwd seg aggregates
__device__ unsigned g_cf[NSEG * NCQ];    // 2 MB fwd carries
__device__ unsigned g_cb[NSEG * NCQ];    // 2 MB bwd carries
__device__ double             g_bce;
__device__ unsigned long long g_total;
__device__ unsigned long long g_cnt;

__global__ void init_kernel() {
    g_bce = 0.0; g_total = 0ULL; g_cnt = 0ULL;
}

// K1: stream pred+targ once (float4/uint4). Per (col-quad, 16-row segment):
// BCE partials, count, local fwd+bwd byte scans, write (pb<<7)|d_local bytes,
// and byte-packed segment aggregates A (fwd carry-out), B (bwd carry source).
__global__ __launch_bounds__(256) void k1_kernel(const float4* __restrict__ pred,
                                                 const uint4*  __restrict__ targ) {
    unsigned gid = blockIdx.x * 256u + threadIdx.x;
    unsigned cq  = gid & (NCQ - 1);
    unsigned seg = gid >> 13;
    // float4/uint4 element index for row i of this quad
    unsigned base4 = (cq >> 8) * 262144u + (seg * SLEN) * 256u + (cq & 255u);

    unsigned f4 = 0xFFFFFFFFu;     // "inf" (saturates; self-caps at 127 via a4)
    unsigned farr[SLEN];           // f_local bytes | pb<<7
    float bce = 0.0f;
    unsigned cnt = 0;

#pragma unroll
    for (int i = 0; i < SLEN; ++i) {
        float4 p = pred[base4 + i * 256u];
        uint4  t = targ[base4 + i * 256u];   // target floats: 0x0 or 0x3F800000

        unsigned nt = ((t.x == 0u) ? 1u : 0u)
                    | ((t.y == 0u) ? 1u : 0u) << 8
                    | ((t.z == 0u) ? 1u : 0u) << 16
                    | ((t.w == 0u) ? 1u : 0u) << 24;          // 0x01 bytes where NOT target
        unsigned pm = ((p.x > 0.0f) ? 1u : 0u)
                    | ((p.y > 0.0f) ? 1u : 0u) << 8
                    | ((p.z > 0.0f) ? 1u : 0u) << 16
                    | ((p.w > 0.0f) ? 1u : 0u) << 24;         // 0x01 bytes where pred>0

        unsigned a4 = nt * 0x7Fu;                             // 0x7F non-target, 0x00 target
        f4 = __vminu4(a4, __vaddus4(f4, 0x01010101u));        // f <= 127 always
        farr[i] = f4 | (pm << 7);

        cnt = __dp4a(pm & nt, 0x01010101u, cnt);              // count(pb & !target)

        // numerically stable BCE-with-logits (targets are exactly 0/1)
        bce += fmaxf(p.x, 0.0f) - (t.x ? p.x : 0.0f) + __logf(1.0f + __expf(-fabsf(p.x)));
        bce += fmaxf(p.y, 0.0f) - (t.y ? p.y : 0.0f) + __logf(1.0f + __expf(-fabsf(p.y)));
        bce += fmaxf(p.z, 0.0f) - (t.z ? p.z : 0.0f) + __logf(1.0f + __expf(-fabsf(p.z)));
        bce += fmaxf(p.w, 0.0f) - (t.w ? p.w : 0.0f) + __logf(1.0f + __expf(-fabsf(p.w)));
    }
    g_A[seg * NCQ + cq] = f4;      // fwd carry-out (bytes <= 127)

    unsigned b4 = 0xFFFFFFFFu;
#pragma unroll
    for (int i = SLEN - 1; i >= 0; --i) {
        unsigned fq  = farr[i] & 0x7F7F7F7Fu;
        unsigned pm7 = farr[i] & 0x80808080u;
        // target <=> f_local == 0
        unsigned tm  = __vcmpeq4(fq, 0u);                     // 0xFF at targets
        unsigned a4  = ~tm & 0x7F7F7F7Fu;
        b4 = __vminu4(a4, __vaddus4(b4, 0x01010101u));
        g_dl[base4 + i * 256u] = __vminu4(fq, b4) | pm7;
    }
    g_B[seg * NCQ + cq] = b4;

    // block reduce bce + cnt
#pragma unroll
    for (int o = 16; o > 0; o >>= 1) {
        bce += __shfl_down_sync(0xffffffffu, bce, o);
        cnt += __shfl_down_sync(0xffffffffu, cnt, o);
    }
    __shared__ float    sb[8];
    __shared__ unsigned sc[8];
    int wid = threadIdx.x >> 5, lid = threadIdx.x & 31;
    if (lid == 0) { sb[wid] = bce; sc[wid] = cnt; }
    __syncthreads();
    if (threadIdx.x == 0) {
        float tb = 0.0f; unsigned tc = 0;
#pragma unroll
        for (int i = 0; i < 8; ++i) { tb += sb[i]; tc += sc[i]; }
        atomicAdd(&g_bce, (double)tb);
        atomicAdd(&g_cnt, (unsigned long long)tc);
    }
}

// K2: byte-SIMD carry propagation across segments, 4 columns per thread,
// fwd threads [0,NCQ), bwd threads [NCQ,2*NCQ).
__global__ __launch_bounds__(128) void k2_kernel() {
    unsigned t  = blockIdx.x * 128u + threadIdx.x;
    unsigned cq = t & (NCQ - 1);
    unsigned c4 = 0xFFFFFFFFu;   // inf
    if (t < NCQ) {
#pragma unroll
        for (int s = 0; s < NSEG; ++s) {
            g_cf[s * NCQ + cq] = c4;
            unsigned A = g_A[s * NCQ + cq];
            c4 = __vminu4(__vaddus4(A, 0x01010101u), __vaddus4(c4, 0x10101010u));
        }
    } else {
#pragma unroll
        for (int s = NSEG - 1; s >= 0; --s) {
            g_cb[s * NCQ + cq] = c4;
            unsigned B = g_B[s * NCQ + cq];
            c4 = __vminu4(__vaddus4(B, 0x01010101u), __vaddus4(c4, 0x10101010u));
        }
    }
}

// K3: dependency-free combine. Thread = (16 columns, one segment):
// d = min(d_local, cf+i, cb+(SLEN-1-i)); total += pb ? d : 0 via saturating ops + dp4a.
__global__ __launch_bounds__(256) void k3_kernel() {
    unsigned gid = blockIdx.x * 256u + threadIdx.x;
    unsigned q   = gid & 2047u;        // 16-column group
    unsigned seg = gid >> 11;
    // uint4 index of row i: n*65536 + (seg*16+i)*64 + (q&63)
    unsigned base16 = (q >> 6) * 65536u + (seg * SLEN) * 64u + (q & 63u);

    uint4 cf = ((const uint4*)g_cf)[seg * 2048u + q];
    uint4 cb = ((const uint4*)g_cb)[seg * 2048u + q];
    unsigned tot = 0u;

#pragma unroll
    for (int i = 0; i < SLEN; ++i) {
        uint4 dl = ((const uint4*)g_dl)[base16 + i * 64u];
        unsigned ri = (unsigned)i * 0x01010101u;
        unsigned rj = (unsigned)(SLEN - 1 - i) * 0x01010101u;
#define LANE(v, c1, c2)                                                          \
        {                                                                        \
            unsigned d4  = (v) & 0x7F7F7F7Fu;                                    \
            unsigned npm = __vcmpeq4((v) & 0x80808080u, 0u); /* 0xFF if pb=0 */  \
            unsigned r   = __vminu4(__vaddus4((c1), ri), __vaddus4((c2), rj));   \
            unsigned dm  = __vminu4(d4, r);                                      \
            tot = __dp4a(__vsubus4(dm, npm), 0x01010101u, tot);                  \
        }
        LANE(dl.x, cf.x, cb.x)
        LANE(dl.y, cf.y, cb.y)
        LANE(dl.z, cf.z, cb.z)
        LANE(dl.w, cf.w, cb.w)
#undef LANE
    }

#pragma unroll
    for (int o = 16; o > 0; o >>= 1)
        tot += __shfl_down_sync(0xffffffffu, tot, o);
    __shared__ unsigned st[8];
    int wid = threadIdx.x >> 5, lid = threadIdx.x & 31;
    if (lid == 0) st[wid] = tot;
    __syncthreads();
    if (threadIdx.x == 0) {
        unsigned tt = 0u;
#pragma unroll
        for (int i = 0; i < 8; ++i) tt += st[i];
        atomicAdd(&g_total, (unsigned long long)tt);
    }
}

__global__ void fin_kernel(float* out) {
    double bce = g_bce / (double)NELEM;
    unsigned long long tot = g_total;
    unsigned long long cnt = g_cnt;
    double border = (tot == 0ULL) ? 0.0
                                  : ((double)tot / (double)(cnt > 1ULL ? cnt : 1ULL));
    out[0] = (float)(bce + sqrt(border));
}

extern "C" void kernel_launch(void* const* d_in, const int* in_sizes, int n_in,
                              void* d_out, int out_size) {
    const float4* pred = (const float4*)d_in[0];
    const uint4*  targ = (const uint4*)d_in[1];
    float* out = (float*)d_out;

    init_kernel<<<1, 1>>>();
    k1_kernel<<<K1_THREADS / 256, 256>>>(pred, targ);
    k2_kernel<<<(2 * NCQ) / 128, 128>>>();
    k3_kernel<<<(2048 * NSEG) / 256, 256>>>();
    fin_kernel<<<1, 1>>>(out);
}

// round 5
// speedup vs baseline: 1.1261x; 1.1261x over previous
#include <cuda_runtime.h>
#include <cuda_bf16.h>
#include <math.h>

#define Hh 1024
#define Ww 1024
#define Nn 32
#define NCOLS 32768
#define NELEM (Nn * Hh * Ww)      // 33554432
#define SLEN 64                   // rows per segment
#define NSEG 16                   // segments per column
#define NCQ (NCOLS / 4)           // 8192 column-quads (one float4 across w)
#define K1_THREADS (NCQ * NSEG)   // 131072
#define BIGD (1 << 20)

// Scratch (__device__ globals: allocation-free per harness rules)
__device__ unsigned long long g_T[NSEG * NCOLS];   // 4 MB target masks  [seg][col]
__device__ unsigned long long g_P[NSEG * NCOLS];   // 4 MB predbin masks
__device__ unsigned g_lo[NSEG * NCQ];              // 512 KB: byte per col = lsb pos (255 = empty)
__device__ unsigned g_hi[NSEG * NCQ];              // 512 KB: byte per col = 63 - msb pos (255 = empty)
__device__ unsigned char g_db[NSEG * NCOLS];       // 512 KB: dist at row -1 of segment (capped 255)
__device__ unsigned char g_du[NSEG * NCOLS];       // 512 KB: dist at row 64 of segment
__device__ double             g_bce;
__device__ unsigned long long g_total;
__device__ unsigned long long g_cnt;

__global__ void init_kernel() {
    g_bce = 0.0; g_total = 0ULL; g_cnt = 0ULL;
}

// K1: stream pred+targ once. Per (col-quad, 64-row segment): BCE partials and
// per-column 64-bit target/pred masks + first/last target positions. No scans.
__global__ __launch_bounds__(256) void k1_kernel(const float4* __restrict__ pred,
                                                 const uint4*  __restrict__ targ) {
    unsigned gid = blockIdx.x * 256u + threadIdx.x;   // 131072
    unsigned cq  = gid & (NCQ - 1);
    unsigned seg = gid >> 13;
    unsigned base4 = (cq >> 8) * 262144u + (seg * SLEN) * 256u + (cq & 255u);

    unsigned Tlo[4] = {0,0,0,0}, Thi[4] = {0,0,0,0};
    unsigned Plo[4] = {0,0,0,0}, Phi[4] = {0,0,0,0};
    float bce = 0.0f;

#pragma unroll
    for (int i = 0; i < 32; ++i) {
        float4 p = __ldcs(&pred[base4 + i * 256u]);
        uint4  t = __ldcs(&targ[base4 + i * 256u]);   // 0x0 or 0x3F800000
        Tlo[0] |= (t.x ? 1u : 0u) << i;  Tlo[1] |= (t.y ? 1u : 0u) << i;
        Tlo[2] |= (t.z ? 1u : 0u) << i;  Tlo[3] |= (t.w ? 1u : 0u) << i;
        Plo[0] |= (p.x > 0.0f) << i;     Plo[1] |= (p.y > 0.0f) << i;
        Plo[2] |= (p.z > 0.0f) << i;     Plo[3] |= (p.w > 0.0f) << i;
        bce += fmaxf(p.x, 0.0f) - (t.x ? p.x : 0.0f) + __logf(1.0f + __expf(-fabsf(p.x)));
        bce += fmaxf(p.y, 0.0f) - (t.y ? p.y : 0.0f) + __logf(1.0f + __expf(-fabsf(p.y)));
        bce += fmaxf(p.z, 0.0f) - (t.z ? p.z : 0.0f) + __logf(1.0f + __expf(-fabsf(p.z)));
        bce += fmaxf(p.w, 0.0f) - (t.w ? p.w : 0.0f) + __logf(1.0f + __expf(-fabsf(p.w)));
    }
#pragma unroll
    for (int i = 0; i < 32; ++i) {
        float4 p = __ldcs(&pred[base4 + (i + 32) * 256u]);
        uint4  t = __ldcs(&targ[base4 + (i + 32) * 256u]);
        Thi[0] |= (t.x ? 1u : 0u) << i;  Thi[1] |= (t.y ? 1u : 0u) << i;
        Thi[2] |= (t.z ? 1u : 0u) << i;  Thi[3] |= (t.w ? 1u : 0u) << i;
        Phi[0] |= (p.x > 0.0f) << i;     Phi[1] |= (p.y > 0.0f) << i;
        Phi[2] |= (p.z > 0.0f) << i;     Phi[3] |= (p.w > 0.0f) << i;
        bce += fmaxf(p.x, 0.0f) - (t.x ? p.x : 0.0f) + __logf(1.0f + __expf(-fabsf(p.x)));
        bce += fmaxf(p.y, 0.0f) - (t.y ? p.y : 0.0f) + __logf(1.0f + __expf(-fabsf(p.y)));
        bce += fmaxf(p.z, 0.0f) - (t.z ? p.z : 0.0f) + __logf(1.0f + __expf(-fabsf(p.z)));
        bce += fmaxf(p.w, 0.0f) - (t.w ? p.w : 0.0f) + __logf(1.0f + __expf(-fabsf(p.w)));
    }

    unsigned midx = seg * NCOLS + 4u * cq;
    unsigned lo4 = 0, hi4 = 0;
#pragma unroll
    for (int c = 0; c < 4; ++c) {
        g_T[midx + c] = (unsigned long long)Tlo[c] | ((unsigned long long)Thi[c] << 32);
        g_P[midx + c] = (unsigned long long)Plo[c] | ((unsigned long long)Phi[c] << 32);
        unsigned lop = Tlo[c] ? (unsigned)(__ffs(Tlo[c]) - 1)
                              : (Thi[c] ? (unsigned)(31 + __ffs(Thi[c])) : 255u);
        unsigned hid = Thi[c] ? (unsigned)__clz(Thi[c])
                              : (Tlo[c] ? (unsigned)(32 + __clz(Tlo[c])) : 255u);
        lo4 |= lop << (8 * c);
        hi4 |= hid << (8 * c);
    }
    g_lo[seg * NCQ + cq] = lo4;
    g_hi[seg * NCQ + cq] = hi4;

    // block reduce bce
#pragma unroll
    for (int o = 16; o > 0; o >>= 1)
        bce += __shfl_down_sync(0xffffffffu, bce, o);
    __shared__ float sb[8];
    int wid = threadIdx.x >> 5, lid = threadIdx.x & 31;
    if (lid == 0) sb[wid] = bce;
    __syncthreads();
    if (threadIdx.x == 0) {
        float tb = 0.0f;
#pragma unroll
        for (int i = 0; i < 8; ++i) tb += sb[i];
        atomicAdd(&g_bce, (double)tb);
    }
}

// K2: per-column boundary-distance recurrences over the 16 segments (exact ints).
__global__ __launch_bounds__(256) void k2_kernel() {
    unsigned col = blockIdx.x * 256u + threadIdx.x;   // 32768
    const unsigned char* lo8 = (const unsigned char*)g_lo;
    const unsigned char* hi8 = (const unsigned char*)g_hi;

    int e = BIGD;   // f_global at last row of previous segment
#pragma unroll
    for (int s = 0; s < NSEG; ++s) {
        g_db[s * NCOLS + col] = (unsigned char)min(e, 255);
        int hi = hi8[s * NCOLS + col];
        e = min(hi == 255 ? BIGD : hi, min(e + SLEN, BIGD));
    }
    int u = BIGD;   // b_global at first row of following segment
#pragma unroll
    for (int s = NSEG - 1; s >= 0; --s) {
        g_du[s * NCOLS + col] = (unsigned char)min(u, 255);
        int lo = lo8[s * NCOLS + col];
        u = min(lo == 255 ? BIGD : lo, min(u + SLEN, BIGD));
    }
}

// K3: bit-parallel grassfire. cover_k = dilate^k(T) | carry prefix | carry suffix;
// total += popc(P & ~cover_k) per level; count = popc(P & ~T).
__global__ __launch_bounds__(256) void k3_kernel() {
    unsigned gid = blockIdx.x * 256u + threadIdx.x;   // 524288
    unsigned col = gid & (NCOLS - 1);
    unsigned seg = gid >> 15;
    unsigned idx = seg * NCOLS + col;

    unsigned long long T = g_T[idx];
    unsigned long long P = g_P[idx];
    int db = g_db[idx];
    int du = g_du[idx];

    unsigned long long M = T, pre = 0ULL, suf = 0ULL;
    unsigned long long rem = P & ~T;
    unsigned cnt = (unsigned)__popcll(rem);
    unsigned tot = 0;
    int k = 0;
    while (rem && k < 1024) {
        tot += (unsigned)__popcll(rem);
        ++k;
        M |= (M << 1) | (M >> 1);
        pre = (pre << 1) | (unsigned long long)(k > db);
        suf = (suf >> 1) | ((k > du) ? 0x8000000000000000ULL : 0ULL);
        rem &= ~(M | pre | suf);
    }

#pragma unroll
    for (int o = 16; o > 0; o >>= 1) {
        tot += __shfl_down_sync(0xffffffffu, tot, o);
        cnt += __shfl_down_sync(0xffffffffu, cnt, o);
    }
    __shared__ unsigned st[8], sc[8];
    int wid = threadIdx.x >> 5, lid = threadIdx.x & 31;
    if (lid == 0) { st[wid] = tot; sc[wid] = cnt; }
    __syncthreads();
    if (threadIdx.x == 0) {
        unsigned tt = 0, tc = 0;
#pragma unroll
        for (int i = 0; i < 8; ++i) { tt += st[i]; tc += sc[i]; }
        atomicAdd(&g_total, (unsigned long long)tt);
        atomicAdd(&g_cnt,   (unsigned long long)tc);
    }
}

__global__ void fin_kernel(float* out) {
    double bce = g_bce / (double)NELEM;
    unsigned long long tot = g_total;
    unsigned long long cnt = g_cnt;
    double border = (tot == 0ULL) ? 0.0
                                  : ((double)tot / (double)(cnt > 1ULL ? cnt : 1ULL));
    out[0] = (float)(bce + sqrt(border));
}

extern "C" void kernel_launch(void* const* d_in, const int* in_sizes, int n_in,
                              void* d_out, int out_size) {
    const float4* pred = (const float4*)d_in[0];
    const uint4*  targ = (const uint4*)d_in[1];
    float* out = (float*)d_out;

    init_kernel<<<1, 1>>>();
    k1_kernel<<<K1_THREADS / 256, 256>>>(pred, targ);
    k2_kernel<<<NCOLS / 256, 256>>>();
    k3_kernel<<<(NSEG * NCOLS) / 256, 256>>>();
    fin_kernel<<<1, 1>>>(out);
}